// round 9
// baseline (speedup 1.0000x reference)
#include <cuda_runtime.h>
#include <cuda_bf16.h>
#include <cstdint>
#include <cstddef>

// ---------------------------------------------------------------- constants
#define B_   8
#define NL_  64
#define NT_  512
#define H_   128
#define E_   2048
#define M_   4096
#define P_TOT (B_*NL_*NT_)          // 262144 pairs

// output layout: tuple flattened in return order, float32
#define OUT_PI 0
#define OUT_SG (P_TOT*10)
#define OUT_MU (P_TOT*20)
#define OUT_CB (P_TOT*30)
#define OUT_AT (OUT_CB + P_TOT)
#define OUT_BT (OUT_AT + 512*18)
#define OUT_CD (OUT_BT + E_*5)
#define OUT_CM (OUT_CD + M_)

// ---------------------------------------------------------------- scratch
__device__ float g_Lh[512*128];     // lig @ W_top, BN folded
__device__ float g_Th[4096*128];    // (pro @ W_bot)*s, row-major [ti][h]
__device__ float g_Ls[512*128];     // selector lig part
__device__ float g_Ts[4096*128];    // selector pro part

// ---------------------------------------------------------------- helpers
__device__ __forceinline__ float eluf(float x) {
    return fmaxf(x, 0.f) + __expf(fminf(x, 0.f)) - 1.f;
}
__device__ __forceinline__ float2 ffma2(float2 a, float2 b, float2 c) {
    float2 d;
    asm("fma.rn.f32x2 %0, %1, %2, %3;"
        : "=l"(reinterpret_cast<unsigned long long&>(d))
        : "l"(reinterpret_cast<unsigned long long&>(a)),
          "l"(reinterpret_cast<unsigned long long&>(b)),
          "l"(reinterpret_cast<unsigned long long&>(c)));
    return d;
}
__device__ __forceinline__ uint32_t smem_u32(const void* p) {
    uint32_t a;
    asm("{ .reg .u64 t; cvta.to.shared.u64 t, %1; cvt.u32.u64 %0, t; }" : "=r"(a) : "l"(p));
    return a;
}
__device__ __forceinline__ void ldsm_x4(uint32_t& r0, uint32_t& r1, uint32_t& r2, uint32_t& r3, uint32_t a) {
    asm volatile("ldmatrix.sync.aligned.m8n8.x4.shared.b16 {%0,%1,%2,%3}, [%4];"
        : "=r"(r0), "=r"(r1), "=r"(r2), "=r"(r3) : "r"(a));
}
__device__ __forceinline__ void ldsm_x2(uint32_t& r0, uint32_t& r1, uint32_t a) {
    asm volatile("ldmatrix.sync.aligned.m8n8.x2.shared.b16 {%0,%1}, [%2];"
        : "=r"(r0), "=r"(r1) : "r"(a));
}
__device__ __forceinline__ void mma_bf16(float* d,
        uint32_t a0, uint32_t a1, uint32_t a2, uint32_t a3,
        uint32_t b0, uint32_t b1) {
    asm volatile("mma.sync.aligned.m16n8k16.row.col.f32.bf16.bf16.f32 "
        "{%0,%1,%2,%3}, {%4,%5,%6,%7}, {%8,%9}, {%0,%1,%2,%3};"
        : "+f"(d[0]), "+f"(d[1]), "+f"(d[2]), "+f"(d[3])
        : "r"(a0), "r"(a1), "r"(a2), "r"(a3), "r"(b0), "r"(b1));
}

// ================================================================ FRONT kernel
#define FRONT_BLOCKS 352

__device__ __forceinline__ void gemm64(
    const float* __restrict__ A, const float* __restrict__ W, int ldw, int wrow0, int N,
    int r0, int c0, int mode,
    const float* __restrict__ g, const float* __restrict__ be,
    const float* __restrict__ m, const float* __restrict__ v,
    const float* __restrict__ lb,
    float* __restrict__ C, int ldc, int transC,
    float (*Ast)[68], float (*Ws)[68]) {

    int tid = threadIdx.x;
    int tx = tid & 15, ty = tid >> 4;
    float2 acc2[4][2] = {};

    for (int kc = 0; kc < 128; kc += 64) {
        #pragma unroll
        for (int q = tid; q < 64 * 16; q += 256) {
            int r = q >> 4, k4 = q & 15;
            float4 val = *(const float4*)(A + (size_t)(r0 + r) * 128 + kc + k4 * 4);
            Ast[k4 * 4 + 0][r] = val.x;
            Ast[k4 * 4 + 1][r] = val.y;
            Ast[k4 * 4 + 2][r] = val.z;
            Ast[k4 * 4 + 3][r] = val.w;
        }
        #pragma unroll
        for (int q = tid; q < 64 * 64; q += 256) {
            int k = q >> 6, c = q & 63;
            float w = 0.f;
            if (c0 + c < N) w = W[(size_t)(wrow0 + kc + k) * ldw + c0 + c];
            Ws[k][c] = w;
        }
        __syncthreads();
        #pragma unroll 16
        for (int k = 0; k < 64; k++) {
            float4 a4 = *(const float4*)&Ast[k][ty * 4];
            float4 w4 = *(const float4*)&Ws[k][tx * 4];
            float2 wlo = make_float2(w4.x, w4.y);
            float2 whi = make_float2(w4.z, w4.w);
            float av[4] = {a4.x, a4.y, a4.z, a4.w};
            #pragma unroll
            for (int d = 0; d < 4; d++) {
                float2 ad = make_float2(av[d], av[d]);
                acc2[d][0] = ffma2(ad, wlo, acc2[d][0]);
                acc2[d][1] = ffma2(ad, whi, acc2[d][1]);
            }
        }
        __syncthreads();
    }

    #pragma unroll
    for (int e = 0; e < 4; e++) {
        int c = c0 + tx * 4 + e;
        if (c >= N) continue;
        float s = 1.f, cb = 0.f;
        if (mode == 0) {
            s = g[c] * rsqrtf(v[c] + 1e-5f);
            cb = (lb[c] - m[c]) * s + be[c];
        } else if (mode == 1) {
            s = g[c] * rsqrtf(v[c] + 1e-5f);
        } else {
            cb = lb[c];
        }
        #pragma unroll
        for (int d = 0; d < 4; d++) {
            int r = r0 + ty * 4 + d;
            float a = (e & 1) ? acc2[d][e >> 1].y : acc2[d][e >> 1].x;
            float val = a * s + cb;
            if (transC) C[(size_t)c * ldc + r] = val;
            else        C[(size_t)r * ldc + c] = val;
        }
    }
}

__global__ void __launch_bounds__(256)
front_kernel(const float* __restrict__ lig_s, const float* __restrict__ pro_s,
             const int* __restrict__ eidx,
             const float* __restrict__ mlp_w, const float* __restrict__ mlp_b,
             const float* __restrict__ mlp_g, const float* __restrict__ mlp_be,
             const float* __restrict__ mlp_m, const float* __restrict__ mlp_v,
             const float* __restrict__ sel_w1, const float* __restrict__ sel_b1,
             const float* __restrict__ sel_g, const float* __restrict__ sel_be,
             const float* __restrict__ sel_m, const float* __restrict__ sel_v,
             const float* __restrict__ at_w, const float* __restrict__ at_b,
             const float* __restrict__ bt_w, const float* __restrict__ bt_b,
             float* __restrict__ Lh, float* __restrict__ Th,
             float* __restrict__ Ls, float* __restrict__ Ts,
             float* __restrict__ out) {
    __shared__ float Ast[64][68];
    __shared__ float Ws[64][68];
    int blk = blockIdx.x;
    int tid = threadIdx.x;

    if (blk < 16) {
        int i = blk;
        gemm64(lig_s, mlp_w, 128, 0, 128, (i >> 1) * 64, (i & 1) * 64, 0,
               mlp_g, mlp_be, mlp_m, mlp_v, mlp_b, Lh, 128, 0, Ast, Ws);
    } else if (blk < 32) {
        int i = blk - 16;
        gemm64(lig_s, sel_w1, 128, 0, 128, (i >> 1) * 64, (i & 1) * 64, 0,
               sel_g, sel_be, sel_m, sel_v, sel_b1, Ls, 128, 0, Ast, Ws);
    } else if (blk < 40) {
        int i = blk - 32;
        gemm64(lig_s, at_w, 18, 0, 18, i * 64, 0, 2,
               nullptr, nullptr, nullptr, nullptr, at_b, out + OUT_AT, 18, 0, Ast, Ws);
    } else if (blk < 168) {
        int i = blk - 40;
        gemm64(pro_s, mlp_w, 128, 128, 128, (i >> 1) * 64, (i & 1) * 64, 1,
               mlp_g, nullptr, nullptr, mlp_v, nullptr, Th, 128, 0, Ast, Ws);
    } else if (blk < 296) {
        int i = blk - 168;
        gemm64(pro_s, sel_w1, 128, 128, 128, (i >> 1) * 64, (i & 1) * 64, 1,
               sel_g, nullptr, nullptr, sel_v, nullptr, Ts, 128, 0, Ast, Ws);
    } else if (blk < 336) {
        int t = (blk - 296) * 256 + tid;
        if (t < E_ * 5) {
            int e = t / 5, c = t - e * 5;
            int e0 = eidx[e], e1 = eidx[E_ + e];
            float acc = bt_b[c];
            const float* r0 = lig_s + (size_t)e0 * 128;
            const float* r1 = lig_s + (size_t)e1 * 128;
            #pragma unroll 4
            for (int k = 0; k < 128; k++) acc = fmaf(r0[k], __ldg(bt_w + k * 5 + c), acc);
            #pragma unroll 4
            for (int k = 0; k < 128; k++) acc = fmaf(r1[k], __ldg(bt_w + (128 + k) * 5 + c), acc);
            out[OUT_BT + t] = acc;
        }
    } else {
        int base = (blk - 336) * 4096;
        float4* cb = (float4*)(out + OUT_CB);
        float4* cm = (float4*)(out + OUT_CM);
        const float4 ones = make_float4(1.f, 1.f, 1.f, 1.f);
        #pragma unroll
        for (int it = 0; it < 16; it++) {
            int q = base + it * 256 + tid;
            float b = (float)((q * 4) >> 15);
            cb[q] = make_float4(b, b, b, b);
            cm[q] = ones;
        }
    }
}

// ================================================================ BACK kernel (mma.sync)
// blocks [0,128): pair MDN. block = (b, ig in 0..3 [16 lig], jh in 0..3 [128 pro]),
//   16 stages of 128 pairs. Per stage:
//   A: q = max(x,0)+exp(min(x,0)) once per (pair,h), bf16 hi/lo into smem.
//   B: 16 warps, warp = (mtb, nt): m16n8k16 mma, 3 segments (hi*whi+lo*whi+hi*wlo),
//      B fragments preloaded in regs once per block. D -> smem Dbuf.
//   C: epilogue (softmax/elu, Sg fold) from Dbuf -> gmem.
// blocks [128,144): donor selector.
#define OFF_TH   0            // 128*132 f32 = 67584 B
#define OFF_L    67584        // 16*128 f32  = 8192 B
#define OFF_SG   75776        // 32 f32      = 128 B
#define OFF_WHI  75904        // 32*136 bf16 = 8704 B
#define OFF_WLO  84608        // 8704 B
#define OFF_QHI  93312        // 128*136 bf16 = 34816 B
#define OFF_QLO  128128       // 34816 B
#define OFF_DB   162944       // 128*34 f32 = 17408 B
#define SMEM_BACK 180352
#define BACK_BLOCKS 144

__global__ void __launch_bounds__(512, 1)
back_kernel(const float* __restrict__ Lh, const float* __restrict__ Th,
            const float* __restrict__ Ls, const float* __restrict__ Ts,
            const float* __restrict__ pi_w, const float* __restrict__ pi_b,
            const float* __restrict__ sg_w, const float* __restrict__ sg_b,
            const float* __restrict__ mu_w, const float* __restrict__ mu_b,
            const int* __restrict__ donar_idx,
            const float* __restrict__ sel_w2, const float* __restrict__ sel_b2,
            float* __restrict__ out) {
    int tid = threadIdx.x;
    int blk = blockIdx.x;

    if (blk >= 128) {
        // ---------------- donor selector: 16 blocks x 16 warps ----------------
        int w = tid >> 5, lane = tid & 31;
        float w2v[4];
        #pragma unroll
        for (int hq = 0; hq < 4; hq++) w2v[hq] = __ldg(sel_w2 + lane + hq * 32);
        float b2 = __ldg(sel_b2);
        #pragma unroll 2
        for (int it = 0; it < 16; it++) {
            int mm = (blk - 128) * 256 + it * 16 + w;
            int p = donar_idx[mm];
            int li = p / 512;
            int ti = (p >> 15) * 512 + (p & 511);
            float acc = 0.f;
            #pragma unroll
            for (int hq = 0; hq < 4; hq++) {
                int h = lane + hq * 32;
                float x = Ls[(size_t)li * 128 + h] + Ts[(size_t)ti * 128 + h];
                acc = fmaf(eluf(x), w2v[hq], acc);
            }
            #pragma unroll
            for (int o = 16; o; o >>= 1) acc += __shfl_xor_sync(0xffffffffu, acc, o);
            if (lane == 0) out[OUT_CD + mm] = 1.f / (1.f + __expf(-(acc + b2)));
        }
        return;
    }

    // ---------------- pairwise MDN ----------------
    extern __shared__ float sm[];
    char* smc = (char*)sm;
    uint32_t sb = smem_u32(sm);

    int b  = blk >> 4;          // 0..7
    int ig = (blk >> 2) & 3;    // 0..3 (16 lig rows each)
    int jh = blk & 3;           // 0..3 (128 pro each)
    int li_base = b * 64 + ig * 16;
    int ti_base = b * 512 + jh * 128;

    int w = tid >> 5, lane = tid & 31;

    // ---- staging: Th, L, W(bf16 hi/lo), Sg ----
    #pragma unroll
    for (int q = tid; q < 128 * 32; q += 512) {
        int j = q >> 5, h4 = q & 31;
        float4 v = *(const float4*)(Th + (size_t)(ti_base + j) * 128 + h4 * 4);
        *(float4*)(sm + j * 132 + h4 * 4) = v;
    }
    {
        int r = tid >> 5, k4 = tid & 31;   // 16 rows x 32 float4 = 512
        *(float4*)(sm + OFF_L / 4 + r * 128 + k4 * 4) =
            *(const float4*)(Lh + (size_t)(li_base + r) * 128 + k4 * 4);
    }
    #pragma unroll
    for (int q = tid; q < 32 * 128; q += 512) {
        int n = q >> 7, h = q & 127;
        float wv = (n < 10) ? pi_w[h * 10 + n]
                 : (n < 20) ? sg_w[h * 10 + n - 10]
                 : (n < 30) ? mu_w[h * 10 + n - 20]
                            : 0.f;
        __nv_bfloat16 hi = __float2bfloat16(wv);
        __nv_bfloat16 lo = __float2bfloat16(wv - __bfloat162float(hi));
        *(__nv_bfloat16*)(smc + OFF_WHI + n * 272 + h * 2) = hi;
        *(__nv_bfloat16*)(smc + OFF_WLO + n * 272 + h * 2) = lo;
    }
    if (tid < 32) {
        float s = 0.f;
        if (tid < 30) {
            for (int h = 0; h < 128; h++) {
                s += (tid < 10) ? pi_w[h * 10 + tid]
                   : (tid < 20) ? sg_w[h * 10 + tid - 10]
                                : mu_w[h * 10 + tid - 20];
            }
        }
        sm[OFF_SG / 4 + tid] = s;
    }
    __syncthreads();

    // ---- per-warp constants & B-fragment preload (once) ----
    int nt  = w & 3;            // n-tile 0..3  (heads nt*8..+7)
    int mtb = w >> 2;           // m-tiles mtb and mtb+4

    uint32_t b_addr = sb + OFF_WHI + (uint32_t)(nt * 8 + (lane & 7)) * 272
                    + ((lane & 8) ? 16u : 0u);
    uint32_t bhi0[8], bhi1[8], blo0[8], blo1[8];
    #pragma unroll
    for (int ks = 0; ks < 8; ks++) {
        ldsm_x2(bhi0[ks], bhi1[ks], b_addr + ks * 32);
        ldsm_x2(blo0[ks], blo1[ks], b_addr + (OFF_WLO - OFF_WHI) + ks * 32);
    }

    // A-fragment lane addressing (ldmatrix x4)
    uint32_t a_row  = (uint32_t)((lane & 7) + (lane & 8));
    uint32_t a_koff = (lane & 16) ? 16u : 0u;

    // Phase-A thread mapping: pair p = tid&127, h chunk hq = tid>>7
    int pA = tid & 127;
    int hq = tid >> 7;
    int h0 = hq * 32;
    const float4* T4 = (const float4*)(sm + pA * 132 + h0);
    uint4* qh4 = (uint4*)(smc + OFF_QHI + pA * 272 + h0 * 2);
    uint4* ql4 = (uint4*)(smc + OFF_QLO + pA * 272 + h0 * 2);

    for (int s = 0; s < 16; s++) {
        // ---- Phase A: q -> bf16 hi/lo into smem ----
        {
            const float4* L4 = (const float4*)(sm + OFF_L / 4 + s * 128 + h0);
            #pragma unroll
            for (int g = 0; g < 4; g++) {       // 8 h per iter
                float4 ta = T4[2 * g], tb = T4[2 * g + 1];
                float4 la = L4[2 * g], lb = L4[2 * g + 1];
                float x[8] = { ta.x + la.x, ta.y + la.y, ta.z + la.z, ta.w + la.w,
                               tb.x + lb.x, tb.y + lb.y, tb.z + lb.z, tb.w + lb.w };
                float qv[8];
                #pragma unroll
                for (int i = 0; i < 8; i++)
                    qv[i] = fmaxf(x[i], 0.f) + __expf(fminf(x[i], 0.f));
                uint32_t hw[4], lw[4];
                #pragma unroll
                for (int j = 0; j < 4; j++) {
                    __nv_bfloat162 h2 = __floats2bfloat162_rn(qv[2 * j], qv[2 * j + 1]);
                    float2 hf = __bfloat1622float2(h2);
                    __nv_bfloat162 l2 = __floats2bfloat162_rn(qv[2 * j] - hf.x, qv[2 * j + 1] - hf.y);
                    hw[j] = *reinterpret_cast<uint32_t*>(&h2);
                    lw[j] = *reinterpret_cast<uint32_t*>(&l2);
                }
                qh4[g] = make_uint4(hw[0], hw[1], hw[2], hw[3]);
                ql4[g] = make_uint4(lw[0], lw[1], lw[2], lw[3]);
            }
        }
        __syncthreads();

        // ---- Phase B: mma ----
        float d[2][4] = {};
        #pragma unroll
        for (int ks = 0; ks < 8; ks++) {
            #pragma unroll
            for (int m = 0; m < 2; m++) {
                int mt = mtb + m * 4;
                uint32_t ah = sb + OFF_QHI + (uint32_t)(mt * 16 + a_row) * 272
                            + ks * 32 + a_koff;
                uint32_t h0r, h1r, h2r, h3r, l0r, l1r, l2r, l3r;
                ldsm_x4(h0r, h1r, h2r, h3r, ah);
                ldsm_x4(l0r, l1r, l2r, l3r, ah + (OFF_QLO - OFF_QHI));
                mma_bf16(d[m], h0r, h1r, h2r, h3r, bhi0[ks], bhi1[ks]);
                mma_bf16(d[m], l0r, l1r, l2r, l3r, bhi0[ks], bhi1[ks]);
                mma_bf16(d[m], h0r, h1r, h2r, h3r, blo0[ks], blo1[ks]);
            }
        }
        // write D fragments to Dbuf
        #pragma unroll
        for (int m = 0; m < 2; m++) {
            int mt = mtb + m * 4;
            int r  = mt * 16 + (lane >> 2);
            int nc = nt * 8 + (lane & 3) * 2;
            float* Db = sm + OFF_DB / 4 + r * 34 + nc;
            *(float2*)Db            = make_float2(d[m][0], d[m][1]);
            *(float2*)(Db + 8 * 34) = make_float2(d[m][2], d[m][3]);
        }
        __syncthreads();

        // ---- Phase C: epilogue (256 threads) ----
        if (tid < 256) {
            int p  = tid >> 1;
            int kh = tid & 1;
            const float* Db = sm + OFF_DB / 4 + p * 34 + kh * 16;
            float acc[16];
            #pragma unroll
            for (int i = 0; i < 16; i++) acc[i] = Db[i];
            const float* Sg = sm + OFF_SG / 4;
            int li = li_base + s;
            size_t pair = (size_t)li * 512 + jh * 128 + p;

            if (kh == 0) {
                float v[10];
                #pragma unroll
                for (int k = 0; k < 10; k++) v[k] = acc[k] + __ldg(pi_b + k) - Sg[k];
                float mx = v[0];
                #pragma unroll
                for (int k = 1; k < 10; k++) mx = fmaxf(mx, v[k]);
                float ssum = 0.f;
                #pragma unroll
                for (int k = 0; k < 10; k++) { v[k] = __expf(v[k] - mx); ssum += v[k]; }
                float inv = 1.0f / ssum;
                float2* dp = (float2*)(out + OUT_PI + pair * 10);
                #pragma unroll
                for (int k = 0; k < 5; k++) dp[k] = make_float2(v[2*k] * inv, v[2*k+1] * inv);
                float s6[6];
                #pragma unroll
                for (int i = 0; i < 6; i++)
                    s6[i] = eluf(acc[10 + i] + __ldg(sg_b + i) - Sg[10 + i]) + 1.1f;
                float2* ds = (float2*)(out + OUT_SG + pair * 10);
                ds[0] = make_float2(s6[0], s6[1]);
                ds[1] = make_float2(s6[2], s6[3]);
                ds[2] = make_float2(s6[4], s6[5]);
            } else {
                float s4[4];
                #pragma unroll
                for (int i = 0; i < 4; i++)
                    s4[i] = eluf(acc[i] + __ldg(sg_b + 6 + i) - Sg[16 + i]) + 1.1f;
                float2* ds = (float2*)(out + OUT_SG + pair * 10 + 6);
                ds[0] = make_float2(s4[0], s4[1]);
                ds[1] = make_float2(s4[2], s4[3]);
                float mv[10];
                #pragma unroll
                for (int i = 0; i < 10; i++)
                    mv[i] = eluf(acc[4 + i] + __ldg(mu_b + i) - Sg[20 + i]) + 1.0f;
                float2* dm = (float2*)(out + OUT_MU + pair * 10);
                #pragma unroll
                for (int k = 0; k < 5; k++) dm[k] = make_float2(mv[2*k], mv[2*k+1]);
            }
        }
        __syncthreads();   // protect Qhi/Qlo + Dbuf rewrite next stage
    }
}

// ================================================================ launch
extern "C" void kernel_launch(void* const* d_in, const int* in_sizes, int n_in,
                              void* d_out, int out_size) {
    const float* lig_s  = (const float*)d_in[0];
    const float* pro_s  = (const float*)d_in[1];
    const int*   donar  = (const int*)d_in[4];
    const int*   eidx   = (const int*)d_in[5];
    const float* mlp_w  = (const float*)d_in[6];
    const float* mlp_b  = (const float*)d_in[7];
    const float* mlp_g  = (const float*)d_in[8];
    const float* mlp_be = (const float*)d_in[9];
    const float* mlp_m  = (const float*)d_in[10];
    const float* mlp_v  = (const float*)d_in[11];
    const float* sel_w1 = (const float*)d_in[12];
    const float* sel_b1 = (const float*)d_in[13];
    const float* sel_g  = (const float*)d_in[14];
    const float* sel_be = (const float*)d_in[15];
    const float* sel_m  = (const float*)d_in[16];
    const float* sel_v  = (const float*)d_in[17];
    const float* sel_w2 = (const float*)d_in[18];
    const float* sel_b2 = (const float*)d_in[19];
    const float* pi_w   = (const float*)d_in[20];
    const float* pi_b   = (const float*)d_in[21];
    const float* sg_w   = (const float*)d_in[22];
    const float* sg_b   = (const float*)d_in[23];
    const float* mu_w   = (const float*)d_in[24];
    const float* mu_b   = (const float*)d_in[25];
    const float* at_w   = (const float*)d_in[26];
    const float* at_b   = (const float*)d_in[27];
    const float* bt_w   = (const float*)d_in[28];
    const float* bt_b   = (const float*)d_in[29];
    float* out = (float*)d_out;

    float *Lh, *Th, *Ls, *Ts;
    cudaGetSymbolAddress((void**)&Lh, g_Lh);
    cudaGetSymbolAddress((void**)&Th, g_Th);
    cudaGetSymbolAddress((void**)&Ls, g_Ls);
    cudaGetSymbolAddress((void**)&Ts, g_Ts);

    cudaFuncSetAttribute((const void*)back_kernel,
                         cudaFuncAttributeMaxDynamicSharedMemorySize, SMEM_BACK);

    front_kernel<<<FRONT_BLOCKS, 256>>>(
        lig_s, pro_s, eidx,
        mlp_w, mlp_b, mlp_g, mlp_be, mlp_m, mlp_v,
        sel_w1, sel_b1, sel_g, sel_be, sel_m, sel_v,
        at_w, at_b, bt_w, bt_b,
        Lh, Th, Ls, Ts, out);

    back_kernel<<<BACK_BLOCKS, 512, SMEM_BACK>>>(
        Lh, Th, Ls, Ts,
        pi_w, pi_b, sg_w, sg_b, mu_w, mu_b,
        donar, sel_w2, sel_b2, out);
}